// round 13
// baseline (speedup 1.0000x reference)
#include <cuda_runtime.h>
#include <stdint.h>

#define NSITES   144
#define NHID     256
#define G3       768
#define BATCH    1024
#define NB       8
#define NBLOCKS  (BATCH / NB)
#define THREADS  1024
#define NQ       4
#define KQ       (NHID / NQ)       // 64 k-iters per thread
#define HSTRIDE  12                // h_s row stride (floats): 48B rows, 16B-aligned

// dynamic smem layout (bytes)
#define RED_OFF  0
#define RED_SZ   (12 * NQ * NHID * 8)                 // 98304: red[slot][q][j] u64
#define H_OFF    (RED_OFF + RED_SZ)
#define H_SZ     (NHID * HSTRIDE * 4)                 // 12288
#define GX_OFF   (H_OFF + H_SZ)
#define GX_SZ    (3 * G3 * 4)                         // 9216
#define GUM_OFF  (GX_OFF + GX_SZ)
#define GUM_SZ   (NSITES * NB * 2 * 4)                // 9216
#define S_OFF    (GUM_OFF + GUM_SZ)
#define SMEM_TOTAL (S_OFF + 64)                       // ~129 KB

// ---------------- threefry2x32 core (JAX schedule) ----------------
__device__ __forceinline__ uint32_t rotl32(uint32_t x, uint32_t r) {
    return __funnelshift_l(x, x, r);
}

__device__ __forceinline__ void tf2x32(uint32_t k0, uint32_t k1,
                                       uint32_t x0, uint32_t x1,
                                       uint32_t &o0, uint32_t &o1) {
    uint32_t k2 = k0 ^ k1 ^ 0x1BD11BDAu;
    x0 += k0; x1 += k1;
#define TFR(r) { x0 += x1; x1 = rotl32(x1, r); x1 ^= x0; }
    TFR(13) TFR(15) TFR(26) TFR(6)    x0 += k1; x1 += k2 + 1u;
    TFR(17) TFR(29) TFR(16) TFR(24)   x0 += k2; x1 += k0 + 2u;
    TFR(13) TFR(15) TFR(26) TFR(6)    x0 += k0; x1 += k1 + 3u;
    TFR(17) TFR(29) TFR(16) TFR(24)   x0 += k1; x1 += k2 + 4u;
    TFR(13) TFR(15) TFR(26) TFR(6)    x0 += k2; x1 += k0 + 5u;
#undef TFR
    o0 = x0; o1 = x1;
}

// Partitionable random_bits (32-bit): element i = w0 ^ w1 of tf2x32(key, (0, i))
__device__ __forceinline__ uint32_t rbits_part(uint32_t k0, uint32_t k1, uint32_t i) {
    uint32_t o0, o1;
    tf2x32(k0, k1, 0u, i, o0, o1);
    return o0 ^ o1;
}

// jax.random.gumbel: -log(-log(uniform(tiny, 1)))
__device__ __forceinline__ float gumbel_from(uint32_t bits) {
    const float TINY = 1.17549435e-38f;
    float f = __uint_as_float((bits >> 9) | 0x3f800000u) - 1.0f;
    float u = fmaxf(TINY, f + TINY);
    return -logf(-logf(u));
}

// ---------------- packed f32x2 ops (sm_100+) ----------------
__device__ __forceinline__ void fma2(unsigned long long &d, unsigned long long a,
                                     unsigned long long b) {
    asm("fma.rn.f32x2 %0, %1, %2, %0;" : "+l"(d) : "l"(a), "l"(b));
}
__device__ __forceinline__ unsigned long long pack2(float x) {
    unsigned long long r;
    asm("mov.b64 %0, {%1, %1};" : "=l"(r) : "f"(x));
    return r;
}
__device__ __forceinline__ unsigned long long add2(unsigned long long a,
                                                   unsigned long long b) {
    unsigned long long r;
    asm("add.rn.f32x2 %0, %1, %2;" : "=l"(r) : "l"(a), "l"(b));
    return r;
}
__device__ __forceinline__ void unpack2(unsigned long long v, float &lo, float &hi) {
    asm("mov.b64 {%0, %1}, %2;" : "=f"(lo), "=f"(hi) : "l"(v));
}

__device__ __forceinline__ float sigmoid_x(float x) {
    return 0.5f + 0.5f * tanhf(0.5f * x);
}

__global__ void __launch_bounds__(THREADS, 1)
rnn_sample_kernel(const float* __restrict__ Wx,    // kernel      [2, 768]
                  const float* __restrict__ Wh,    // rec_kernel  [256, 768]
                  const float* __restrict__ bias,  // [2, 768]
                  const float* __restrict__ Dw,    // dense_w     [256, 2]
                  const float* __restrict__ Db,    // dense_b     [2]
                  float* __restrict__ out)         // samples [1024,144] then logP [1024]
{
    extern __shared__ __align__(16) char smem_raw[];
    unsigned long long* red = reinterpret_cast<unsigned long long*>(smem_raw + RED_OFF);
    float* h_s  = reinterpret_cast<float*>(smem_raw + H_OFF);   // [k][b], stride 12
    float* gx_s = reinterpret_cast<float*>(smem_raw + GX_OFF);  // [x-case][col]
    float* gum  = reinterpret_cast<float*>(smem_raw + GUM_OFF); // [t][b][cls]
    int*   s_arr = reinterpret_cast<int*>(smem_raw + S_OFF);

    const int tid  = threadIdx.x;
    const int lane = tid & 31;
    const int warp = tid >> 5;
    const int j    = tid & 255;      // gate unit (coalesced within warp)
    const int q    = tid >> 8;       // k-quarter AND sample-pair owner
    const int bbase = blockIdx.x * NB;

    // ---- one-time init ----
    for (int i = tid; i < NHID * HSTRIDE; i += THREADS) h_s[i] = 0.0f;
    for (int c = tid; c < G3; c += THREADS) {
        float b0 = bias[c];
        gx_s[c]          = b0;              // x = 0 (t=0)
        gx_s[G3 + c]     = Wx[c] + b0;      // one_hot(0)
        gx_s[2 * G3 + c] = Wx[G3 + c] + b0; // one_hot(1)
    }
    for (int i = tid; i < NSITES * NB * 2; i += THREADS) {
        int t = i >> 4, r = i & 15;
        int b = r >> 1, cls = r & 1;
        uint32_t o0, o1;
        tf2x32(0u, 42u, 0u, (uint32_t)t, o0, o1);       // partitionable split -> step key
        gum[i] = gumbel_from(rbits_part(o0, o1, (uint32_t)(2 * (bbase + b) + cls)));
    }
    if (tid < NB) s_arr[tid] = -1;
    float logP = 0.0f;   // lane 0 of warps 0..7 (sample = warp id)
    __syncthreads();

    const float b1z = bias[G3 + j], b1r = bias[G3 + 256 + j], b1n = bias[G3 + 512 + j];
    const float db0 = Db[0], db1 = Db[1];
    const int k0 = q * KQ;
    const float* wbase = Wh + k0 * G3 + j;
    const float* hbase0 = h_s + k0 * HSTRIDE;

    for (int i = 0; i < NSITES; ++i) {
        // ======== phase 1: k-loop over this thread's quarter ========
        unsigned long long acc[12];
#pragma unroll
        for (int a = 0; a < 12; ++a) acc[a] = 0ull;
        const float* wp = wbase;
#pragma unroll 4
        for (int k = 0; k < KQ; ++k) {
            unsigned long long w0 = pack2(wp[0]);
            unsigned long long w1 = pack2(wp[256]);
            unsigned long long w2 = pack2(wp[512]);
            wp += G3;
            const ulonglong2* hp =
                reinterpret_cast<const ulonglong2*>(hbase0 + k * HSTRIDE);
            ulonglong2 hA = hp[0], hB = hp[1];
            fma2(acc[0], w0, hA.x); fma2(acc[1], w0, hA.y);
            fma2(acc[2], w0, hB.x); fma2(acc[3], w0, hB.y);
            fma2(acc[4], w1, hA.x); fma2(acc[5], w1, hA.y);
            fma2(acc[6], w1, hB.x); fma2(acc[7], w1, hB.y);
            fma2(acc[8], w2, hA.x); fma2(acc[9], w2, hA.y);
            fma2(acc[10], w2, hB.x); fma2(acc[11], w2, hB.y);
        }
        // publish partials: red[slot][q][j] (consecutive-j u64, conflict-free)
#pragma unroll
        for (int s = 0; s < 12; ++s) red[(s * NQ + q) * NHID + j] = acc[s];

        // head for step i-1 (warps 0-7; h_s stable during phase 1)
        if (warp < NB && i > 0) {
            const int b = warp, t = i - 1;
            float c0 = 0.0f, c1 = 0.0f;
            for (int k = lane; k < NHID; k += 32) {
                float hv = h_s[k * HSTRIDE + b];
                c0 += hv * Dw[2 * k];
                c1 += hv * Dw[2 * k + 1];
            }
#pragma unroll
            for (int off = 16; off > 0; off >>= 1) {
                c0 += __shfl_down_sync(0xffffffffu, c0, off);
                c1 += __shfl_down_sync(0xffffffffu, c1, off);
            }
            if (lane == 0) {
                float la = c0 + db0, lb = c1 + db1;
                float m  = fmaxf(la, lb);
                float ea = expf(la - m), eb = expf(lb - m);
                float sm = ea + eb;
                float lp0 = logf(1e-10f + ea / sm);
                float lp1 = logf(1e-10f + eb / sm);
                float g0 = gum[(t * NB + b) * 2];
                float g1 = gum[(t * NB + b) * 2 + 1];
                int s = (g1 + lp1 > g0 + lp0) ? 1 : 0;   // argmax ties -> index 0
                logP += s ? lp1 : lp0;
                s_arr[b] = s;
                out[(bbase + b) * NSITES + t] = (float)s;
            }
        }
        __syncthreads();   // red ready; s_arr ready; all h reads done

        // ======== phase 2: combine quarters (ascending k) + gates for pair q ========
        {
            // slots for my pair: z=q, r=4+q, n=8+q; sum src quarters 0->3
            unsigned long long sz, sr, sn;
            {
                const unsigned long long* rz = red + (q * NQ) * NHID + j;
                const unsigned long long* rr = red + ((4 + q) * NQ) * NHID + j;
                const unsigned long long* rn = red + ((8 + q) * NQ) * NHID + j;
                sz = (0 == q) ? acc[q]     : rz[0];
                sr = (0 == q) ? acc[4 + q] : rr[0];
                sn = (0 == q) ? acc[8 + q] : rn[0];
#pragma unroll
                for (int src = 1; src < NQ; ++src) {
                    sz = add2(sz, (src == q) ? acc[q]     : rz[src * NHID]);
                    sr = add2(sr, (src == q) ? acc[4 + q] : rr[src * NHID]);
                    sn = add2(sn, (src == q) ? acc[8 + q] : rn[src * NHID]);
                }
            }
            float gz[2], gr[2], gn[2];
            unpack2(sz, gz[0], gz[1]);
            unpack2(sr, gr[0], gr[1]);
            unpack2(sn, gn[0], gn[1]);
#pragma unroll
            for (int u = 0; u < 2; ++u) {
                int b = 2 * q + u;
                int idx = s_arr[b] + 1;                 // -1 -> 0 (x = 0 at t=0)
                float gxz = gx_s[idx * G3 + j];
                float gxr = gx_s[idx * G3 + 256 + j];
                float gxn = gx_s[idx * G3 + 512 + j];
                float z  = sigmoid_x(gxz + gz[u] + b1z);
                float r  = sigmoid_x(gxr + gr[u] + b1r);
                float hh = tanhf(gxn + r * (gn[u] + b1n));
                float hold = h_s[j * HSTRIDE + b];
                h_s[j * HSTRIDE + b] = z * hold + (1.0f - z) * hh;
            }
        }
        __syncthreads();   // h ready for next k-loop / head
    }

    // ======== epilogue head: step NSITES-1 from final h ========
    if (warp < NB) {
        const int b = warp, t = NSITES - 1;
        float c0 = 0.0f, c1 = 0.0f;
        for (int k = lane; k < NHID; k += 32) {
            float hv = h_s[k * HSTRIDE + b];
            c0 += hv * Dw[2 * k];
            c1 += hv * Dw[2 * k + 1];
        }
#pragma unroll
        for (int off = 16; off > 0; off >>= 1) {
            c0 += __shfl_down_sync(0xffffffffu, c0, off);
            c1 += __shfl_down_sync(0xffffffffu, c1, off);
        }
        if (lane == 0) {
            float la = c0 + db0, lb = c1 + db1;
            float m  = fmaxf(la, lb);
            float ea = expf(la - m), eb = expf(lb - m);
            float sm = ea + eb;
            float lp0 = logf(1e-10f + ea / sm);
            float lp1 = logf(1e-10f + eb / sm);
            float g0 = gum[(t * NB + b) * 2];
            float g1 = gum[(t * NB + b) * 2 + 1];
            int s = (g1 + lp1 > g0 + lp0) ? 1 : 0;
            logP += s ? lp1 : lp0;
            out[(bbase + b) * NSITES + t] = (float)s;
            out[BATCH * NSITES + bbase + b] = logP;
        }
    }
}

extern "C" void kernel_launch(void* const* d_in, const int* in_sizes, int n_in,
                              void* d_out, int out_size) {
    (void)in_sizes; (void)n_in; (void)out_size;
    const float* Wx   = (const float*)d_in[0];
    const float* Wh   = (const float*)d_in[1];
    const float* bias = (const float*)d_in[2];
    const float* Dw   = (const float*)d_in[3];
    const float* Db   = (const float*)d_in[4];
    float* out = (float*)d_out;
    cudaFuncSetAttribute(rnn_sample_kernel,
                         cudaFuncAttributeMaxDynamicSharedMemorySize, SMEM_TOTAL);
    rnn_sample_kernel<<<NBLOCKS, THREADS, SMEM_TOTAL>>>(Wx, Wh, bias, Dw, Db, out);
}